// round 9
// baseline (speedup 1.0000x reference)
#include <cuda_runtime.h>

#define B_    16
#define CIN_  256
#define COUT_ 3
#define WDIM_ 512
#define INS   128
#define OUTS  256
#define FW    13
#define TR    16      // output rows per upsample tile
#define IR    14      // input rows needed per tile (TR/2 + 6)
#define CSPL  2       // channel splits in einsum
#define CPB   (CIN_ / CSPL)   // 128 channels per block
#define PLN   (INS * INS)     // 16384 px per plane
#define BCP   (B_ * COUT_)    // 48 planes

// scratch (allocation-free rule: __device__ globals)
__device__ float g_c[B_ * COUT_ * CIN_];               // combined per-(b,o,i) weight
__device__ float g_kf[FW];                             // 2 * reversed filter
__device__ float g_part[CSPL * BCP * PLN];             // unclamped partial sums

// ---- packed f32x2 helpers ---------------------------------------------------
__device__ __forceinline__ unsigned long long pack2(float lo, float hi) {
    unsigned long long r;
    asm("mov.b64 %0, {%1, %2};" : "=l"(r) : "f"(lo), "f"(hi));
    return r;
}
#define FFMA2(acc, a, b) \
    asm("fma.rn.f32x2 %0, %1, %2, %0;" : "+l"(acc) : "l"(a), "l"(b))

// ---------------------------------------------------------------------------
// K1: styles + combined weights + filter prep
// one warp per (b,i) dot product: 4096 warps = 1024 blocks x 4 warps
__global__ void k_styles(const float* __restrict__ w,
                         const float* __restrict__ aw,
                         const float* __restrict__ abias,
                         const float* __restrict__ cw,
                         const float* __restrict__ filt) {
    const int wg   = blockIdx.x * 4 + (threadIdx.x >> 5);
    const int lane = threadIdx.x & 31;
    const int b    = wg >> 8;
    const int i    = wg & 255;

    const float4* wr4 = (const float4*)(w + (size_t)b * WDIM_);
    const float4* ar4 = (const float4*)(aw + (size_t)i * WDIM_);
    float s = 0.f;
    #pragma unroll
    for (int q = 0; q < 4; q++) {
        float4 a = ar4[q * 32 + lane];
        float4 v = wr4[q * 32 + lane];
        s += a.x * v.x + a.y * v.y + a.z * v.z + a.w * v.w;
    }
    #pragma unroll
    for (int off = 16; off; off >>= 1)
        s += __shfl_down_sync(0xffffffffu, s, off);
    if (lane == 0) {
        float style = (s * 0.04419417382415922f /*1/sqrt(512)*/ + abias[i])
                      * 0.0625f /*1/sqrt(256)*/;
        #pragma unroll
        for (int o = 0; o < COUT_; o++)
            g_c[(b * COUT_ + o) * CIN_ + i] = cw[o * CIN_ + i] * style;
    }
    if (blockIdx.x == 0 && threadIdx.x < FW)
        g_kf[threadIdx.x] = 2.0f * filt[FW - 1 - threadIdx.x];
}

// ---------------------------------------------------------------------------
// K2: split-C partial einsum. Each block reduces 128 channels over 256 px.
// grid (64 px-tiles, 16 b, 2 csplit) = 2048 blocks, 128 threads, 2 px/thread.
// float2 loads land directly in a 64-bit reg = one fma.rn.f32x2 operand.
__global__ void k_einsum(const float* __restrict__ x) {
    const int b    = blockIdx.y;
    const int s    = blockIdx.z;
    const int base = blockIdx.x * 256 + threadIdx.x * 2;

    // 128 channels x 3 outputs of modulation weights, duplicated (c,c)
    __shared__ unsigned long long c2[COUT_ * CPB];
    {
        int t = threadIdx.x;                 // 128 threads, 3 each
        const float* gc = g_c + b * COUT_ * CIN_ + s * CPB;
        #pragma unroll
        for (int o = 0; o < COUT_; o++) {
            float v = gc[o * CIN_ + t];
            c2[o * CPB + t] = pack2(v, v);
        }
    }
    __syncthreads();

    unsigned long long a0 = 0ull, a1 = 0ull, a2 = 0ull;

    const float* xb = x + ((size_t)b * CIN_ + s * CPB) * PLN + base;
    #pragma unroll 16
    for (int j = 0; j < CPB; j++) {
        unsigned long long v = *(const unsigned long long*)(xb + j * PLN);
        FFMA2(a0, c2[j], v);
        FFMA2(a1, c2[CPB + j], v);
        FFMA2(a2, c2[2 * CPB + j], v);
    }

    float* pp = g_part + ((size_t)(s * BCP + b * COUT_)) * PLN + base;
    *(unsigned long long*)(pp)           = a0;
    *(unsigned long long*)(pp + PLN)     = a1;
    *(unsigned long long*)(pp + 2 * PLN) = a2;
}

// ---------------------------------------------------------------------------
// K3: combine partials + bias + clamp, then fused separable polyphase x2
// upsample (H then V in shared memory). grid (48 planes, 16 row-tiles), 256 thr.
__global__ void k_upfused(float* __restrict__ out,
                          const float* __restrict__ cbias) {
    const int plane = blockIdx.x;          // b*3 + o
    const int tile  = blockIdx.y;
    const int r0    = tile * TR;           // first output row (even)
    const int s0    = r0 >> 1;             // first "center" input row
    const int tid   = threadIdx.x;
    const float bia = cbias[plane % COUT_];

    __shared__ float kf[FW];
    __shared__ float in_s[IR][INS];
    __shared__ float h_s[IR][OUTS];

    if (tid < FW) kf[tid] = g_kf[tid];

    // stage input rows s0-3 .. s0+10: sum 2 partials + bias, clamp; 0 outside
    const float* pp = g_part + (size_t)plane * PLN;
    #pragma unroll
    for (int idx = tid; idx < IR * INS; idx += 256) {
        int r  = idx >> 7;
        int c  = idx & (INS - 1);
        int gr = s0 - 3 + r;
        float v = 0.f;
        if (gr >= 0 && gr < INS) {
            int off = gr * INS + c;
            float sum = pp[off] + pp[(size_t)BCP * PLN + off];
            v = fminf(fmaxf(sum + bia, -256.f), 256.f);
        }
        in_s[r][c] = v;
    }
    __syncthreads();

    // ---- horizontal: output col n = tid, all IR rows ----
    {
        const int n   = tid;
        const int par = n & 1;
        const int cb  = (n >> 1) - 3;
        float wt[7];
        int   cc[7];
        #pragma unroll
        for (int j = 0; j < 7; j++) {
            int c   = cb + j;
            float v = par ? kf[2 * j] : ((j < 6) ? kf[2 * j + 1] : 0.f);
            bool ok = (c >= 0 && c < INS);
            cc[j] = ok ? c : 0;
            wt[j] = ok ? v : 0.f;
        }
        #pragma unroll
        for (int r = 0; r < IR; r++) {
            float acc = 0.f;
            #pragma unroll
            for (int j = 0; j < 7; j++)
                acc += wt[j] * in_s[r][cc[j]];
            h_s[r][n] = acc;
        }
    }
    __syncthreads();

    // ---- vertical: col = tid; cache the 14 column samples in registers ----
    float hv[IR];
    #pragma unroll
    for (int r = 0; r < IR; r++) hv[r] = h_s[r][tid];

    float* op = out + ((size_t)plane * OUTS + r0) * OUTS + tid;
    #pragma unroll
    for (int k = 0; k < TR; k++) {
        const int lrb = k >> 1;            // r0 even -> local base row = k>>1
        float acc = 0.f;
        if (k & 1) {
            #pragma unroll
            for (int j = 0; j < 7; j++)
                acc += kf[2 * j] * hv[lrb + j];
        } else {
            #pragma unroll
            for (int j = 0; j < 6; j++)
                acc += kf[2 * j + 1] * hv[lrb + j];
        }
        op[k * OUTS] = acc;
    }
}

// ---------------------------------------------------------------------------
extern "C" void kernel_launch(void* const* d_in, const int* in_sizes, int n_in,
                              void* d_out, int out_size) {
    const float* x     = (const float*)d_in[0];  // [16,256,128,128]
    const float* w     = (const float*)d_in[1];  // [16,512]
    const float* aw    = (const float*)d_in[2];  // [256,512]
    const float* ab    = (const float*)d_in[3];  // [256]
    const float* cw    = (const float*)d_in[4];  // [3,256,1,1]
    const float* cb    = (const float*)d_in[5];  // [3]
    const float* filt  = (const float*)d_in[6];  // [13]
    float* out = (float*)d_out;                  // [16,3,256,256]

    k_styles<<<1024, 128>>>(w, aw, ab, cw, filt);
    k_einsum<<<dim3(64, B_, CSPL), 128>>>(x);
    k_upfused<<<dim3(BCP, OUTS / TR), 256>>>(out, cb);
}

// round 10
// speedup vs baseline: 1.0254x; 1.0254x over previous
#include <cuda_runtime.h>

#define B_    16
#define CIN_  256
#define COUT_ 3
#define WDIM_ 512
#define INS   128
#define OUTS  256
#define FW    13
#define TR    16      // output rows per upsample tile
#define IR    14      // input rows needed per tile (TR/2 + 6)
#define CSPL  4       // channel splits in einsum
#define CPB   (CIN_ / CSPL)   // 64 channels per block
#define PLN   (INS * INS)     // 16384 px per plane
#define BCP   (B_ * COUT_)    // 48 planes

// scratch (allocation-free rule: __device__ globals)
__device__ float g_part[CSPL * BCP * PLN];             // unclamped partial sums

// ---- packed f32x2 helpers ---------------------------------------------------
__device__ __forceinline__ unsigned long long pack2(float lo, float hi) {
    unsigned long long r;
    asm("mov.b64 %0, {%1, %2};" : "=l"(r) : "f"(lo), "f"(hi));
    return r;
}
__device__ __forceinline__ void unpack2(unsigned long long v, float& lo, float& hi) {
    asm("mov.b64 {%0, %1}, %2;" : "=f"(lo), "=f"(hi) : "l"(v));
}
#define FFMA2(acc, a, b) \
    asm("fma.rn.f32x2 %0, %1, %2, %0;" : "+l"(acc) : "l"(a), "l"(b))

// ---------------------------------------------------------------------------
// K1: fused styles + split-C partial einsum.
// grid (16 px-tiles, 16 b, 4 csplit) = 1024 blocks, 256 threads.
// Prologue: 8 warps x 8 channels compute the modulated weights for this
// (b, split) 64-channel slice (w row register-cached per lane, coalesced aw
// loads, shuffle reduce). Main: 4 px (float4)/thread over 64 channels.
__global__ void __launch_bounds__(256) k_einsum(
        const float* __restrict__ x,
        const float* __restrict__ w,
        const float* __restrict__ aw,
        const float* __restrict__ abias,
        const float* __restrict__ cw) {
    const int b    = blockIdx.y;
    const int s    = blockIdx.z;
    const int tid  = threadIdx.x;
    const int lane = tid & 31;
    const int wid  = tid >> 5;

    __shared__ unsigned long long c2[COUT_ * CPB];

    // ---- phase A: styles for channels [s*64, s*64+64) ----
    {
        const float4* w4 = (const float4*)(w + (size_t)b * WDIM_);
        float4 wv0 = w4[lane];
        float4 wv1 = w4[32 + lane];
        float4 wv2 = w4[64 + lane];
        float4 wv3 = w4[96 + lane];
        #pragma unroll
        for (int c8 = 0; c8 < 8; c8++) {
            const int i  = s * CPB + wid * 8 + c8;   // global channel
            const float4* a4 = (const float4*)(aw + (size_t)i * WDIM_);
            float4 av0 = a4[lane];
            float4 av1 = a4[32 + lane];
            float4 av2 = a4[64 + lane];
            float4 av3 = a4[96 + lane];
            float sacc = av0.x * wv0.x + av0.y * wv0.y + av0.z * wv0.z + av0.w * wv0.w
                       + av1.x * wv1.x + av1.y * wv1.y + av1.z * wv1.z + av1.w * wv1.w
                       + av2.x * wv2.x + av2.y * wv2.y + av2.z * wv2.z + av2.w * wv2.w
                       + av3.x * wv3.x + av3.y * wv3.y + av3.z * wv3.z + av3.w * wv3.w;
            #pragma unroll
            for (int off = 16; off; off >>= 1)
                sacc += __shfl_xor_sync(0xffffffffu, sacc, off);
            if (lane == 0) {
                float style = (sacc * 0.04419417382415922f /*1/sqrt(512)*/
                               + abias[i]) * 0.0625f /*1/sqrt(256)*/;
                const int j = wid * 8 + c8;          // local channel 0..63
                #pragma unroll
                for (int o = 0; o < COUT_; o++) {
                    float v = cw[o * CIN_ + i] * style;
                    c2[o * CPB + j] = pack2(v, v);
                }
            }
        }
    }
    __syncthreads();

    // ---- phase B: streaming channel reduction (R8 config) ----
    const int base = blockIdx.x * 1024 + tid * 4;

    unsigned long long a00 = 0ull, a01 = 0ull;
    unsigned long long a10 = 0ull, a11 = 0ull;
    unsigned long long a20 = 0ull, a21 = 0ull;

    const float* xb = x + ((size_t)b * CIN_ + s * CPB) * PLN + base;
    #pragma unroll 8
    for (int j = 0; j < CPB; j++) {
        float4 v = __ldcs((const float4*)(xb + (size_t)j * PLN));
        unsigned long long vlo = pack2(v.x, v.y);
        unsigned long long vhi = pack2(v.z, v.w);
        unsigned long long c0 = c2[j];
        unsigned long long c1 = c2[CPB + j];
        unsigned long long ck = c2[2 * CPB + j];
        FFMA2(a00, c0, vlo); FFMA2(a01, c0, vhi);
        FFMA2(a10, c1, vlo); FFMA2(a11, c1, vhi);
        FFMA2(a20, ck, vlo); FFMA2(a21, ck, vhi);
    }

    unsigned long long alo[3] = {a00, a10, a20};
    unsigned long long ahi[3] = {a01, a11, a21};
    #pragma unroll
    for (int o = 0; o < COUT_; o++) {
        float4 r;
        unpack2(alo[o], r.x, r.y);
        unpack2(ahi[o], r.z, r.w);
        *(float4*)(g_part + ((size_t)(s * BCP + b * COUT_ + o)) * PLN + base) = r;
    }
}

// ---------------------------------------------------------------------------
// K2: combine partials + bias + clamp, then fused separable polyphase x2
// upsample (H then V in shared memory). grid (48 planes, 16 row-tiles), 256 thr.
__global__ void k_upfused(float* __restrict__ out,
                          const float* __restrict__ cbias,
                          const float* __restrict__ filt) {
    const int plane = blockIdx.x;          // b*3 + o
    const int tile  = blockIdx.y;
    const int r0    = tile * TR;           // first output row (even)
    const int s0    = r0 >> 1;             // first "center" input row
    const int tid   = threadIdx.x;
    const float bia = cbias[plane % COUT_];

    __shared__ float kf[FW];
    __shared__ float in_s[IR][INS];
    __shared__ float h_s[IR][OUTS];

    if (tid < FW) kf[tid] = 2.0f * filt[FW - 1 - tid];

    // stage input rows s0-3 .. s0+10: sum 4 partials + bias, clamp; 0 outside
    const float* pp = g_part + (size_t)plane * PLN;
    #pragma unroll
    for (int idx = tid; idx < IR * INS; idx += 256) {
        int r  = idx >> 7;
        int c  = idx & (INS - 1);
        int gr = s0 - 3 + r;
        float v = 0.f;
        if (gr >= 0 && gr < INS) {
            int off = gr * INS + c;
            float sum = pp[off]
                      + pp[1 * (size_t)BCP * PLN + off]
                      + pp[2 * (size_t)BCP * PLN + off]
                      + pp[3 * (size_t)BCP * PLN + off];
            v = fminf(fmaxf(sum + bia, -256.f), 256.f);
        }
        in_s[r][c] = v;
    }
    __syncthreads();

    // ---- horizontal: output col n = tid, all IR rows ----
    {
        const int n   = tid;
        const int par = n & 1;
        const int cb  = (n >> 1) - 3;
        float wt[7];
        int   cc[7];
        #pragma unroll
        for (int j = 0; j < 7; j++) {
            int c   = cb + j;
            float v = par ? kf[2 * j] : ((j < 6) ? kf[2 * j + 1] : 0.f);
            bool ok = (c >= 0 && c < INS);
            cc[j] = ok ? c : 0;
            wt[j] = ok ? v : 0.f;
        }
        #pragma unroll
        for (int r = 0; r < IR; r++) {
            float acc = 0.f;
            #pragma unroll
            for (int j = 0; j < 7; j++)
                acc += wt[j] * in_s[r][cc[j]];
            h_s[r][n] = acc;
        }
    }
    __syncthreads();

    // ---- vertical: col = tid; cache the 14 column samples in registers ----
    float hv[IR];
    #pragma unroll
    for (int r = 0; r < IR; r++) hv[r] = h_s[r][tid];

    float* op = out + ((size_t)plane * OUTS + r0) * OUTS + tid;
    #pragma unroll
    for (int k = 0; k < TR; k++) {
        const int lrb = k >> 1;            // r0 even -> local base row = k>>1
        float acc = 0.f;
        if (k & 1) {
            #pragma unroll
            for (int j = 0; j < 7; j++)
                acc += kf[2 * j] * hv[lrb + j];
        } else {
            #pragma unroll
            for (int j = 0; j < 6; j++)
                acc += kf[2 * j + 1] * hv[lrb + j];
        }
        op[k * OUTS] = acc;
    }
}

// ---------------------------------------------------------------------------
extern "C" void kernel_launch(void* const* d_in, const int* in_sizes, int n_in,
                              void* d_out, int out_size) {
    const float* x     = (const float*)d_in[0];  // [16,256,128,128]
    const float* w     = (const float*)d_in[1];  // [16,512]
    const float* aw    = (const float*)d_in[2];  // [256,512]
    const float* ab    = (const float*)d_in[3];  // [256]
    const float* cw    = (const float*)d_in[4];  // [3,256,1,1]
    const float* cb    = (const float*)d_in[5];  // [3]
    const float* filt  = (const float*)d_in[6];  // [13]
    float* out = (float*)d_out;                  // [16,3,256,256]

    k_einsum<<<dim3(16, B_, CSPL), 256>>>(x, w, aw, ab, cw);
    k_upfused<<<dim3(BCP, OUTS / TR), 256>>>(out, cb, filt);
}

// round 12
// speedup vs baseline: 1.2199x; 1.1896x over previous
#include <cuda_runtime.h>

#define B_    16
#define CIN_  256
#define COUT_ 3
#define WDIM_ 512
#define INS   128
#define OUTS  256
#define FW    13
#define TR    32                  // output rows per upsample tile
#define IR2   22                  // input rows staged per tile (TR/2 + 6)
#define CSPL  4                   // channel splits in einsum
#define CPB   (CIN_ / CSPL)       // 64 channels per block
#define PLN   (INS * INS)         // 16384 px per plane
#define BCP   (B_ * COUT_)        // 48 planes

// scratch (allocation-free rule: __device__ globals)
__device__ float g_part[CSPL * BCP * PLN];             // unclamped partial sums

// ---- packed f32x2 helpers ---------------------------------------------------
__device__ __forceinline__ unsigned long long pack2(float lo, float hi) {
    unsigned long long r;
    asm("mov.b64 %0, {%1, %2};" : "=l"(r) : "f"(lo), "f"(hi));
    return r;
}
__device__ __forceinline__ void unpack2(unsigned long long v, float& lo, float& hi) {
    asm("mov.b64 {%0, %1}, %2;" : "=f"(lo), "=f"(hi) : "l"(v));
}
#define FFMA2(acc, a, b) \
    asm("fma.rn.f32x2 %0, %1, %2, %0;" : "+l"(acc) : "l"(a), "l"(b))

// ---------------------------------------------------------------------------
// K1: fused styles + split-C partial einsum.
// grid (8 px-tiles, 16 b, 4 csplit) = 512 blocks, 512 threads (2 blocks/SM).
// Prologue: 16 warps x 4 channels compute modulated weights for this
// (b, split) 64-channel slice. Main: 4 px (float4)/thread over 64 channels.
__global__ void __launch_bounds__(512, 2) k_einsum(
        const float* __restrict__ x,
        const float* __restrict__ w,
        const float* __restrict__ aw,
        const float* __restrict__ abias,
        const float* __restrict__ cw) {
    const int b    = blockIdx.y;
    const int s    = blockIdx.z;
    const int tid  = threadIdx.x;
    const int lane = tid & 31;
    const int wid  = tid >> 5;   // 0..15

    __shared__ __align__(16) unsigned long long c2[COUT_ * CPB];

    // ---- phase A: styles for channels [s*64, s*64+64) ----
    {
        const float4* w4 = (const float4*)(w + (size_t)b * WDIM_);
        float4 wv0 = w4[lane];
        float4 wv1 = w4[32 + lane];
        float4 wv2 = w4[64 + lane];
        float4 wv3 = w4[96 + lane];
        #pragma unroll
        for (int c8 = 0; c8 < 4; c8++) {
            const int i  = s * CPB + wid * 4 + c8;   // global channel
            const float4* a4 = (const float4*)(aw + (size_t)i * WDIM_);
            float4 av0 = a4[lane];
            float4 av1 = a4[32 + lane];
            float4 av2 = a4[64 + lane];
            float4 av3 = a4[96 + lane];
            float sacc = av0.x * wv0.x + av0.y * wv0.y + av0.z * wv0.z + av0.w * wv0.w
                       + av1.x * wv1.x + av1.y * wv1.y + av1.z * wv1.z + av1.w * wv1.w
                       + av2.x * wv2.x + av2.y * wv2.y + av2.z * wv2.z + av2.w * wv2.w
                       + av3.x * wv3.x + av3.y * wv3.y + av3.z * wv3.z + av3.w * wv3.w;
            #pragma unroll
            for (int off = 16; off; off >>= 1)
                sacc += __shfl_xor_sync(0xffffffffu, sacc, off);
            if (lane == 0) {
                float style = (sacc * 0.04419417382415922f /*1/sqrt(512)*/
                               + abias[i]) * 0.0625f /*1/sqrt(256)*/;
                const int j = wid * 4 + c8;          // local channel 0..63
                #pragma unroll
                for (int o = 0; o < COUT_; o++) {
                    float v = cw[o * CIN_ + i] * style;
                    c2[o * CPB + j] = pack2(v, v);
                }
            }
        }
    }
    __syncthreads();

    // ---- phase B: streaming channel reduction ----
    const int base = blockIdx.x * 2048 + tid * 4;

    unsigned long long a00 = 0ull, a01 = 0ull;
    unsigned long long a10 = 0ull, a11 = 0ull;
    unsigned long long a20 = 0ull, a21 = 0ull;

    const float* xb = x + ((size_t)b * CIN_ + s * CPB) * PLN + base;
    #pragma unroll 8
    for (int j = 0; j < CPB; j++) {
        float4 v = __ldcs((const float4*)(xb + (size_t)j * PLN));
        unsigned long long vlo = pack2(v.x, v.y);
        unsigned long long vhi = pack2(v.z, v.w);
        unsigned long long c0 = c2[j];
        unsigned long long c1 = c2[CPB + j];
        unsigned long long ck = c2[2 * CPB + j];
        FFMA2(a00, c0, vlo); FFMA2(a01, c0, vhi);
        FFMA2(a10, c1, vlo); FFMA2(a11, c1, vhi);
        FFMA2(a20, ck, vlo); FFMA2(a21, ck, vhi);
    }

    unsigned long long alo[3] = {a00, a10, a20};
    unsigned long long ahi[3] = {a01, a11, a21};
    #pragma unroll
    for (int o = 0; o < COUT_; o++) {
        float4 r;
        unpack2(alo[o], r.x, r.y);
        unpack2(ahi[o], r.z, r.w);
        *(float4*)(g_part + ((size_t)(s * BCP + b * COUT_ + o)) * PLN + base) = r;
    }
}

// ---------------------------------------------------------------------------
// K2: combine partials + bias + clamp, then fused separable polyphase x2
// upsample. grid (48 planes, 8 row-tiles of 32), 256 threads.
__global__ void __launch_bounds__(256) k_upfused(
        float* __restrict__ out,
        const float* __restrict__ cbias,
        const float* __restrict__ filt) {
    const int plane = blockIdx.x;          // b*3 + o
    const int tile  = blockIdx.y;
    const int r0    = tile * TR;           // first output row (even)
    const int s0    = r0 >> 1;             // first "center" input row
    const int tid   = threadIdx.x;
    const float bia = cbias[plane % COUT_];

    // 16-byte aligned: in_s/h_s are accessed with LDS.128/STS.128
    __shared__ __align__(16) float in_s[IR2][INS];
    __shared__ __align__(16) float h_s[IR2][OUTS];
    __shared__ __align__(16) float kf[16];           // padded to 16 floats

    if (tid < FW) kf[tid] = 2.0f * filt[FW - 1 - tid];

    // stage rows s0-3 .. s0+18: float4 combine of 4 partials + bias + clamp
    const float* pp = g_part + (size_t)plane * PLN;
    for (int idx = tid; idx < IR2 * (INS / 4); idx += 256) {
        int r  = idx >> 5;                 // /32 float4 per row
        int c4 = idx & 31;
        int gr = s0 - 3 + r;
        float4 v = make_float4(0.f, 0.f, 0.f, 0.f);
        if (gr >= 0 && gr < INS) {
            size_t off = (size_t)gr * INS + c4 * 4;
            float4 p0 = *(const float4*)(pp + off);
            float4 p1 = *(const float4*)(pp + 1 * (size_t)BCP * PLN + off);
            float4 p2 = *(const float4*)(pp + 2 * (size_t)BCP * PLN + off);
            float4 p3 = *(const float4*)(pp + 3 * (size_t)BCP * PLN + off);
            v.x = fminf(fmaxf(p0.x + p1.x + p2.x + p3.x + bia, -256.f), 256.f);
            v.y = fminf(fmaxf(p0.y + p1.y + p2.y + p3.y + bia, -256.f), 256.f);
            v.z = fminf(fmaxf(p0.z + p1.z + p2.z + p3.z + bia, -256.f), 256.f);
            v.w = fminf(fmaxf(p0.w + p1.w + p2.w + p3.w + bia, -256.f), 256.f);
        }
        *(float4*)&in_s[r][c4 * 4] = v;
    }
    __syncthreads();

    // ---- horizontal: output col n = tid, all IR2 rows ----
    {
        const int n   = tid;
        const int par = n & 1;
        const int cb  = (n >> 1) - 3;
        float wt[7];
        int   cc[7];
        #pragma unroll
        for (int j = 0; j < 7; j++) {
            int c   = cb + j;
            float v = par ? kf[2 * j] : ((j < 6) ? kf[2 * j + 1] : 0.f);
            bool ok = (c >= 0 && c < INS);
            cc[j] = ok ? c : 0;
            wt[j] = ok ? v : 0.f;
        }
        #pragma unroll
        for (int r = 0; r < IR2; r++) {
            float acc = 0.f;
            #pragma unroll
            for (int j = 0; j < 7; j++)
                acc += wt[j] * in_s[r][cc[j]];
            h_s[r][n] = acc;
        }
    }
    __syncthreads();

    // ---- vertical: col = tid; cache the 22 column samples in registers ----
    float hv[IR2];
    #pragma unroll
    for (int r = 0; r < IR2; r++) hv[r] = h_s[r][tid];

    float* op = out + ((size_t)plane * OUTS + r0) * OUTS + tid;
    #pragma unroll
    for (int k = 0; k < TR; k++) {
        const int lrb = k >> 1;            // r0 even -> local base row = k>>1
        float acc = 0.f;
        if (k & 1) {
            #pragma unroll
            for (int j = 0; j < 7; j++)
                acc += kf[2 * j] * hv[lrb + j];
        } else {
            #pragma unroll
            for (int j = 0; j < 6; j++)
                acc += kf[2 * j + 1] * hv[lrb + j];
        }
        op[k * OUTS] = acc;
    }
}

// ---------------------------------------------------------------------------
extern "C" void kernel_launch(void* const* d_in, const int* in_sizes, int n_in,
                              void* d_out, int out_size) {
    const float* x     = (const float*)d_in[0];  // [16,256,128,128]
    const float* w     = (const float*)d_in[1];  // [16,512]
    const float* aw    = (const float*)d_in[2];  // [256,512]
    const float* ab    = (const float*)d_in[3];  // [256]
    const float* cw    = (const float*)d_in[4];  // [3,256,1,1]
    const float* cb    = (const float*)d_in[5];  // [3]
    const float* filt  = (const float*)d_in[6];  // [13]
    float* out = (float*)d_out;                  // [16,3,256,256]

    k_einsum<<<dim3(8, B_, CSPL), 512>>>(x, w, aw, ab, cw);
    k_upfused<<<dim3(BCP, OUTS / TR), 256>>>(out, cb, filt);
}

// round 13
// speedup vs baseline: 1.2255x; 1.0046x over previous
#include <cuda_runtime.h>

#define B_    16
#define CIN_  256
#define COUT_ 3
#define WDIM_ 512
#define INS   128
#define OUTS  256
#define FW    13
#define TR    32                  // output rows per upsample tile
#define IR2   22                  // input rows staged per tile (TR/2 + 6)
#define CSPL  4                   // channel splits in einsum
#define CPB   (CIN_ / CSPL)       // 64 channels per block
#define PLN   (INS * INS)         // 16384 px per plane
#define BCP   (B_ * COUT_)        // 48 planes

// scratch (allocation-free rule: __device__ globals)
__device__ float g_part[CSPL * BCP * PLN];             // unclamped partial sums

// ---- packed f32x2 helpers ---------------------------------------------------
__device__ __forceinline__ unsigned long long pack2(float lo, float hi) {
    unsigned long long r;
    asm("mov.b64 %0, {%1, %2};" : "=l"(r) : "f"(lo), "f"(hi));
    return r;
}
__device__ __forceinline__ void unpack2(unsigned long long v, float& lo, float& hi) {
    asm("mov.b64 {%0, %1}, %2;" : "=f"(lo), "=f"(hi) : "l"(v));
}
#define FFMA2(acc, a, b) \
    asm("fma.rn.f32x2 %0, %1, %2, %0;" : "+l"(acc) : "l"(a), "l"(b))

// ---------------------------------------------------------------------------
// K1: fused styles + split-C partial einsum.
// grid (8 px-tiles, 16 b, 4 csplit) = 512 blocks, 512 threads (2 blocks/SM).
__global__ void __launch_bounds__(512, 2) k_einsum(
        const float* __restrict__ x,
        const float* __restrict__ w,
        const float* __restrict__ aw,
        const float* __restrict__ abias,
        const float* __restrict__ cw) {
    const int b    = blockIdx.y;
    const int s    = blockIdx.z;
    const int tid  = threadIdx.x;
    const int lane = tid & 31;
    const int wid  = tid >> 5;   // 0..15

    __shared__ __align__(16) unsigned long long c2[COUT_ * CPB];

    // ---- phase A: styles for channels [s*64, s*64+64) ----
    {
        const float4* w4 = (const float4*)(w + (size_t)b * WDIM_);
        float4 wv0 = w4[lane];
        float4 wv1 = w4[32 + lane];
        float4 wv2 = w4[64 + lane];
        float4 wv3 = w4[96 + lane];
        #pragma unroll
        for (int c8 = 0; c8 < 4; c8++) {
            const int i  = s * CPB + wid * 4 + c8;   // global channel
            const float4* a4 = (const float4*)(aw + (size_t)i * WDIM_);
            float4 av0 = a4[lane];
            float4 av1 = a4[32 + lane];
            float4 av2 = a4[64 + lane];
            float4 av3 = a4[96 + lane];
            float sacc = av0.x * wv0.x + av0.y * wv0.y + av0.z * wv0.z + av0.w * wv0.w
                       + av1.x * wv1.x + av1.y * wv1.y + av1.z * wv1.z + av1.w * wv1.w
                       + av2.x * wv2.x + av2.y * wv2.y + av2.z * wv2.z + av2.w * wv2.w
                       + av3.x * wv3.x + av3.y * wv3.y + av3.z * wv3.z + av3.w * wv3.w;
            #pragma unroll
            for (int off = 16; off; off >>= 1)
                sacc += __shfl_xor_sync(0xffffffffu, sacc, off);
            if (lane == 0) {
                float style = (sacc * 0.04419417382415922f /*1/sqrt(512)*/
                               + abias[i]) * 0.0625f /*1/sqrt(256)*/;
                const int j = wid * 4 + c8;          // local channel 0..63
                #pragma unroll
                for (int o = 0; o < COUT_; o++) {
                    float v = cw[o * CIN_ + i] * style;
                    c2[o * CPB + j] = pack2(v, v);
                }
            }
        }
    }
    __syncthreads();

    // ---- phase B: streaming channel reduction ----
    const int base = blockIdx.x * 2048 + tid * 4;

    unsigned long long a00 = 0ull, a01 = 0ull;
    unsigned long long a10 = 0ull, a11 = 0ull;
    unsigned long long a20 = 0ull, a21 = 0ull;

    const float* xb = x + ((size_t)b * CIN_ + s * CPB) * PLN + base;
    #pragma unroll 8
    for (int j = 0; j < CPB; j++) {
        float4 v = __ldcs((const float4*)(xb + (size_t)j * PLN));
        unsigned long long vlo = pack2(v.x, v.y);
        unsigned long long vhi = pack2(v.z, v.w);
        unsigned long long c0 = c2[j];
        unsigned long long c1 = c2[CPB + j];
        unsigned long long ck = c2[2 * CPB + j];
        FFMA2(a00, c0, vlo); FFMA2(a01, c0, vhi);
        FFMA2(a10, c1, vlo); FFMA2(a11, c1, vhi);
        FFMA2(a20, ck, vlo); FFMA2(a21, ck, vhi);
    }

    unsigned long long alo[3] = {a00, a10, a20};
    unsigned long long ahi[3] = {a01, a11, a21};
    #pragma unroll
    for (int o = 0; o < COUT_; o++) {
        float4 r;
        unpack2(alo[o], r.x, r.y);
        unpack2(ahi[o], r.z, r.w);
        *(float4*)(g_part + ((size_t)(s * BCP + b * COUT_ + o)) * PLN + base) = r;
    }
}

// ---------------------------------------------------------------------------
// K2: combine partials + bias + clamp, then fused separable polyphase x2
// upsample. grid (48 planes, 8 row-tiles of 32), 512 threads in two halves:
// half h does H-rows [h*11, h*11+11) and V output rows [h*16, h*16+16).
__global__ void __launch_bounds__(512) k_upfused(
        float* __restrict__ out,
        const float* __restrict__ cbias,
        const float* __restrict__ filt) {
    const int plane = blockIdx.x;          // b*3 + o
    const int tile  = blockIdx.y;
    const int r0    = tile * TR;           // first output row (even)
    const int s0    = r0 >> 1;             // first "center" input row
    const int tid   = threadIdx.x;
    const int col   = tid & 255;
    const int half  = tid >> 8;            // 0 or 1
    const float bia = cbias[plane % COUT_];

    __shared__ __align__(16) float in_s[IR2][INS];
    __shared__ __align__(16) float h_s[IR2][OUTS];
    __shared__ __align__(16) float kf[16];           // padded to 16 floats

    if (tid < FW) kf[tid] = 2.0f * filt[FW - 1 - tid];

    // stage rows s0-3 .. s0+18: float4 combine of 4 partials + bias + clamp
    const float* pp = g_part + (size_t)plane * PLN;
    for (int idx = tid; idx < IR2 * (INS / 4); idx += 512) {
        int r  = idx >> 5;                 // /32 float4 per row
        int c4 = idx & 31;
        int gr = s0 - 3 + r;
        float4 v = make_float4(0.f, 0.f, 0.f, 0.f);
        if (gr >= 0 && gr < INS) {
            size_t off = (size_t)gr * INS + c4 * 4;
            float4 p0 = *(const float4*)(pp + off);
            float4 p1 = *(const float4*)(pp + 1 * (size_t)BCP * PLN + off);
            float4 p2 = *(const float4*)(pp + 2 * (size_t)BCP * PLN + off);
            float4 p3 = *(const float4*)(pp + 3 * (size_t)BCP * PLN + off);
            v.x = fminf(fmaxf(p0.x + p1.x + p2.x + p3.x + bia, -256.f), 256.f);
            v.y = fminf(fmaxf(p0.y + p1.y + p2.y + p3.y + bia, -256.f), 256.f);
            v.z = fminf(fmaxf(p0.z + p1.z + p2.z + p3.z + bia, -256.f), 256.f);
            v.w = fminf(fmaxf(p0.w + p1.w + p2.w + p3.w + bia, -256.f), 256.f);
        }
        *(float4*)&in_s[r][c4 * 4] = v;
    }
    __syncthreads();

    // ---- horizontal: output col n = col; half 0 rows 0..10, half 1 rows 11..21
    {
        const int n   = col;
        const int par = n & 1;
        const int cb  = (n >> 1) - 3;
        float wt[7];
        int   cc[7];
        #pragma unroll
        for (int j = 0; j < 7; j++) {
            int c   = cb + j;
            float v = par ? kf[2 * j] : ((j < 6) ? kf[2 * j + 1] : 0.f);
            bool ok = (c >= 0 && c < INS);
            cc[j] = ok ? c : 0;
            wt[j] = ok ? v : 0.f;
        }
        const int rbase = half * 11;
        #pragma unroll
        for (int r = 0; r < 11; r++) {
            float acc = 0.f;
            #pragma unroll
            for (int j = 0; j < 7; j++)
                acc += wt[j] * in_s[rbase + r][cc[j]];
            h_s[rbase + r][n] = acc;
        }
    }
    __syncthreads();

    // ---- vertical: col = col; half h covers output rows [h*16, h*16+16),
    // needing h_s rows [h*8, h*8+14) -> 14-register column cache.
    float hv[14];
    const int vb = half * 8;
    #pragma unroll
    for (int r = 0; r < 14; r++) hv[r] = h_s[vb + r][col];

    float* op = out + ((size_t)plane * OUTS + r0 + half * 16) * OUTS + col;
    #pragma unroll
    for (int k = 0; k < 16; k++) {
        const int lrb = k >> 1;            // local base row within hv
        float acc = 0.f;
        if (k & 1) {
            #pragma unroll
            for (int j = 0; j < 7; j++)
                acc += kf[2 * j] * hv[lrb + j];
        } else {
            #pragma unroll
            for (int j = 0; j < 6; j++)
                acc += kf[2 * j + 1] * hv[lrb + j];
        }
        op[k * OUTS] = acc;
    }
}

// ---------------------------------------------------------------------------
extern "C" void kernel_launch(void* const* d_in, const int* in_sizes, int n_in,
                              void* d_out, int out_size) {
    const float* x     = (const float*)d_in[0];  // [16,256,128,128]
    const float* w     = (const float*)d_in[1];  // [16,512]
    const float* aw    = (const float*)d_in[2];  // [256,512]
    const float* ab    = (const float*)d_in[3];  // [256]
    const float* cw    = (const float*)d_in[4];  // [3,256,1,1]
    const float* cb    = (const float*)d_in[5];  // [3]
    const float* filt  = (const float*)d_in[6];  // [13]
    float* out = (float*)d_out;                  // [16,3,256,256]

    k_einsum<<<dim3(8, B_, CSPL), 512>>>(x, w, aw, ab, cw);
    k_upfused<<<dim3(BCP, OUTS / TR), 512>>>(out, cb, filt);
}